// round 2
// baseline (speedup 1.0000x reference)
#include <cuda_runtime.h>

#define B_NODES 8192
#define ZS      10
#define INC     512
#define OUTC    512
#define MD      3
#define ALPHA   0.04419417382415922f   // 1/sqrt(512)

// GEMM tiling
#define CT 128          // C (output-channel) tile
#define NT 32           // nodes per tile
#define JT (NT*MD)      // 96 columns
#define KT 16           // k tile
#define NTHREADS 256

// --------- scratch (no cudaMalloc allowed) ----------
__device__ int g_counts[ZS];
__device__ int g_cursor[ZS];
__device__ int g_offsets[ZS + 1];
__device__ int g_species[B_NODES];
__device__ int g_sorted[B_NODES];

// --------- prep kernels ----------
__global__ void k_zero() {
    int i = threadIdx.x;
    if (i < ZS) { g_counts[i] = 0; g_cursor[i] = 0; }
}

__global__ void k_classify(const float* __restrict__ attrs) {
    int b = blockIdx.x * blockDim.x + threadIdx.x;
    if (b >= B_NODES) return;
    int s = 0;
#pragma unroll
    for (int z = 0; z < ZS; z++)
        if (attrs[b * ZS + z] > 0.5f) s = z;
    g_species[b] = s;
    atomicAdd(&g_counts[s], 1);
}

__global__ void k_scan() {
    if (threadIdx.x == 0) {
        int acc = 0;
        for (int z = 0; z < ZS; z++) {
            g_offsets[z] = acc;
            g_cursor[z] = acc;
            acc += g_counts[z];
        }
        g_offsets[ZS] = acc;
    }
}

__global__ void k_scatter() {
    int b = blockIdx.x * blockDim.x + threadIdx.x;
    if (b >= B_NODES) return;
    int s = g_species[b];
    int pos = atomicAdd(&g_cursor[s], 1);
    g_sorted[pos] = b;
}

// --------- main gather-GEMM ----------
// out[node, C, d] = ALPHA * sum_c W[z, C, c] * t[node, c, d]
// grid: x = column tile (over nodes*3 of the species segment, over-launched),
//       y = C tile (4), z = species (10)
__global__ __launch_bounds__(NTHREADS, 4)
void k_gemm(const float* __restrict__ t,
            const float* __restrict__ W,
            float* __restrict__ out)
{
    const int z = blockIdx.z;
    const int count = g_counts[z];
    const int cols  = count * MD;
    const int j0    = blockIdx.x * JT;
    if (j0 >= cols) return;                 // over-launched tile: nothing to do
    const int seg = g_offsets[z];
    const int c0  = blockIdx.y * CT;

    __shared__ float Wsh[KT][CT + 2];       // stride 130 -> conflict-free stores
    __shared__ float Bsh[KT][JT + 4];       // stride 100 -> conflict-free stores
    __shared__ int   nodes[NT];

    const int tid = threadIdx.x;
    if (tid < NT) {
        int ni = j0 / MD + tid;
        nodes[tid] = (ni < count) ? g_sorted[seg + ni] : -1;
    }
    __syncthreads();

    const int tx = tid & 15;                // column group (0..15) -> 6 cols each
    const int ty = tid >> 4;                // row group    (0..15) -> 8 rows each

    float acc[8][6];
#pragma unroll
    for (int i = 0; i < 8; i++)
#pragma unroll
        for (int j = 0; j < 6; j++) acc[i][j] = 0.f;

    const float* Wz = W + (size_t)z * OUTC * INC;

    for (int kk = 0; kk < INC; kk += KT) {
        // W tile: 128 C-rows x 16 k.  16 consecutive threads read 64B/row.
#pragma unroll
        for (int e = tid; e < CT * KT; e += NTHREADS) {
            int c = e >> 4;
            int k = e & 15;
            Wsh[k][c] = Wz[(size_t)(c0 + c) * INC + (kk + k)];
        }
        // B tile: 32 nodes x 48 contiguous floats (t[node, kk:kk+16, 0:3])
#pragma unroll
        for (int e = tid; e < NT * KT * MD; e += NTHREADS) {
            int nl = e / 48;
            int r  = e - nl * 48;           // r = k*3 + d
            int node = nodes[nl];
            float v = 0.f;
            if (node >= 0) v = t[(size_t)node * (INC * MD) + kk * MD + r];
            Bsh[r / 3][nl * 3 + (r % 3)] = v;
        }
        __syncthreads();

#pragma unroll
        for (int k = 0; k < KT; k++) {
            float wv[8], bv[6];
#pragma unroll
            for (int i = 0; i < 8; i++) wv[i] = Wsh[k][ty * 8 + i];
#pragma unroll
            for (int j = 0; j < 6; j++) bv[j] = Bsh[k][tx * 6 + j];
#pragma unroll
            for (int i = 0; i < 8; i++)
#pragma unroll
                for (int j = 0; j < 6; j++)
                    acc[i][j] += wv[i] * bv[j];
        }
        __syncthreads();
    }

    // store: each thread owns 2 nodes x 3 d x 8 C
#pragma unroll
    for (int j = 0; j < 6; j++) {
        int jj = tx * 6 + j;
        int nl = jj / 3, d = jj % 3;
        int node = nodes[nl];
        if (node < 0) continue;
        float* orow = out + (size_t)node * (OUTC * MD) + d;
#pragma unroll
        for (int i = 0; i < 8; i++) {
            int C = c0 + ty * 8 + i;
            orow[(size_t)C * MD] = acc[i][j] * ALPHA;
        }
    }
}

// --------- entry point ----------
extern "C" void kernel_launch(void* const* d_in, const int* in_sizes, int n_in,
                              void* d_out, int out_size)
{
    const float* t     = (const float*)d_in[0];   // [B, IN, M]
    const float* attrs = (const float*)d_in[1];   // [B, Z] one-hot
    const float* W     = (const float*)d_in[2];   // [Z, OUT, IN]
    float* out = (float*)d_out;                   // [B, OUT, M]

    k_zero<<<1, 32>>>();
    k_classify<<<(B_NODES + 255) / 256, 256>>>(attrs);
    k_scan<<<1, 1>>>();
    k_scatter<<<(B_NODES + 255) / 256, 256>>>();

    dim3 grid((B_NODES * MD + JT - 1) / JT,       // 256 col tiles (worst case)
              OUTC / CT,                          // 4
              ZS);                                // 10
    k_gemm<<<grid, NTHREADS>>>(t, W, out);
}

// round 4
// speedup vs baseline: 2.8979x; 2.8979x over previous
#include <cuda_runtime.h>
#include <cstdint>

#define B_NODES 8192
#define ZS      10
#define INC     512
#define OUTC    512
#define MD      3
#define ALPHA   0.04419417382415922f   // 1/sqrt(512)

#define NT      64                     // nodes per block tile
#define NCOLS   (NT*MD)                // 192
#define CT      128                    // C tile
#define KT      16                     // k per stage
#define NSTG    (INC/KT)               // 32
#define NTHREADS 512

#define ASTR    136                    // A smem row stride (floats): (8k+m)%32 conflict-free
#define BSTR    200                    // B smem row stride (floats): (8k+n)%32 conflict-free

// --------- scratch ----------
__device__ int g_counts[ZS];
__device__ int g_cursor[ZS];
__device__ int g_offsets[ZS + 1];
__device__ int g_species[B_NODES];
__device__ int g_sorted[B_NODES];

// --------- prep kernels ----------
__global__ void k_zero() {
    int i = threadIdx.x;
    if (i < ZS) { g_counts[i] = 0; g_cursor[i] = 0; }
}

__global__ void k_classify(const float* __restrict__ attrs) {
    __shared__ int h[ZS];
    int tid = threadIdx.x;
    if (tid < ZS) h[tid] = 0;
    __syncthreads();
    int b = blockIdx.x * blockDim.x + tid;
    int s = 0;
#pragma unroll
    for (int z = 0; z < ZS; z++)
        s = (attrs[b * ZS + z] > 0.5f) ? z : s;
    g_species[b] = s;
    atomicAdd(&h[s], 1);
    __syncthreads();
    if (tid < ZS) atomicAdd(&g_counts[tid], h[tid]);
}

__global__ void k_scan() {
    if (threadIdx.x == 0) {
        int acc = 0;
        for (int z = 0; z < ZS; z++) {
            g_offsets[z] = acc;
            g_cursor[z] = acc;
            acc += g_counts[z];
        }
        g_offsets[ZS] = acc;
    }
}

__global__ void k_scatter() {
    __shared__ int h[ZS], base[ZS];
    int tid = threadIdx.x;
    if (tid < ZS) h[tid] = 0;
    __syncthreads();
    int b = blockIdx.x * blockDim.x + tid;
    int s = g_species[b];
    int lp = atomicAdd(&h[s], 1);
    __syncthreads();
    if (tid < ZS) base[tid] = atomicAdd(&g_cursor[tid], h[tid]);
    __syncthreads();
    g_sorted[base[s] + lp] = b;
}

// --------- helpers ----------
__device__ __forceinline__ uint32_t f2tf32(float f) {
    uint32_t r;
    asm("cvt.rna.tf32.f32 %0, %1;" : "=r"(r) : "f"(f));
    return r;
}
__device__ __forceinline__ void mma_tf32(float* c, const uint32_t* a, const uint32_t* b) {
    asm volatile(
        "mma.sync.aligned.m16n8k8.row.col.f32.tf32.tf32.f32 "
        "{%0,%1,%2,%3}, {%4,%5,%6,%7}, {%8,%9}, {%0,%1,%2,%3};"
        : "+f"(c[0]), "+f"(c[1]), "+f"(c[2]), "+f"(c[3])
        : "r"(a[0]), "r"(a[1]), "r"(a[2]), "r"(a[3]), "r"(b[0]), "r"(b[1]));
}

// --------- tf32 mma.sync gather-GEMM ----------
// D[C, j] = sum_k W[z, c0+C, k] * t[node(j/3), k, j%3]
__global__ __launch_bounds__(NTHREADS, 1)
void k_gemm(const float* __restrict__ t,
            const float* __restrict__ W,
            float* __restrict__ out)
{
    const int z = blockIdx.z;
    const int count = g_counts[z];
    const int n0 = blockIdx.x * NT;
    if (n0 >= count) return;
    const int seg = g_offsets[z];
    const int c0 = blockIdx.y * CT;

    __shared__ float Ash[2][KT][ASTR];     // [k][m]
    __shared__ float Bsh[2][KT][BSTR];     // [k][n],  n = node_l*3 + d
    __shared__ int   nodes[NT];

    const int tid = threadIdx.x;
    if (tid < NT) {
        int ni = n0 + tid;
        nodes[tid] = (ni < count) ? g_sorted[seg + ni] : -1;
    }
    __syncthreads();

    // ---- loader roles ----
    const bool isA = tid < 256;
    const float* wbase = W + ((size_t)z * OUTC + c0) * INC;
    int node_l = 0, part = 0;
    const float* tbase = t;
    bool bvalid = false;
    if (!isA) {
        int t2 = tid - 256;
        node_l = t2 >> 2;                  // 0..63
        part   = t2 & 3;                   // 0..3  -> 12 floats each
        int nd = nodes[node_l];
        bvalid = (nd >= 0);
        tbase = t + (size_t)(bvalid ? nd : 0) * (INC * MD) + part * 12;
    }

    float rA[8], rB[12];

    // ---- compute roles ----
    const int lane = tid & 31;
    const int wid  = tid >> 5;
    const int wm   = wid & 3;              // 0..3 -> M
    const int wn   = wid >> 2;             // 0..3 -> N
    const int g    = lane >> 2;            // 0..7
    const int tg   = lane & 3;             // 0..3

    float acc[2][6][4];
#pragma unroll
    for (int i = 0; i < 2; i++)
#pragma unroll
        for (int j = 0; j < 6; j++)
#pragma unroll
            for (int e = 0; e < 4; e++) acc[i][j][e] = 0.f;

    // ---- gmem -> regs loader ----
    auto gload = [&](int s) {
        const int kk = s * KT;
        if (isA) {
#pragma unroll
            for (int i = 0; i < 2; i++) {
                int e = tid * 2 + i;       // 0..511 float4s
                int m = e >> 2, kq = e & 3;
                float4 v = *(const float4*)(wbase + (size_t)m * INC + kk + kq * 4);
                rA[i*4+0] = v.x; rA[i*4+1] = v.y; rA[i*4+2] = v.z; rA[i*4+3] = v.w;
            }
        } else {
#pragma unroll
            for (int i = 0; i < 3; i++) {
                float4 v = make_float4(0.f, 0.f, 0.f, 0.f);
                if (bvalid) v = *(const float4*)(tbase + kk * MD + i * 4);
                rB[i*4+0] = v.x; rB[i*4+1] = v.y; rB[i*4+2] = v.z; rB[i*4+3] = v.w;
            }
        }
    };
    // ---- regs -> smem (with tf32 rounding) ----
    auto ssts = [&](int buf) {
        if (isA) {
#pragma unroll
            for (int i = 0; i < 2; i++) {
                int e = tid * 2 + i;
                int m = e >> 2, kq = e & 3;
#pragma unroll
                for (int j = 0; j < 4; j++)
                    Ash[buf][kq * 4 + j][m] = __uint_as_float(f2tf32(rA[i*4+j]));
            }
        } else {
#pragma unroll
            for (int p = 0; p < 12; p++) {
                int k = part * 4 + p / 3;
                int d = p % 3;
                Bsh[buf][k][node_l * 3 + d] = __uint_as_float(f2tf32(rB[p]));
            }
        }
    };

    gload(0); ssts(0); __syncthreads();

    for (int s = 0; s < NSTG; s++) {
        const int buf = s & 1;
        if (s + 1 < NSTG) gload(s + 1);

#pragma unroll
        for (int kc = 0; kc < 2; kc++) {
            const int k0 = kc * 8 + tg;
            uint32_t a[2][4];
#pragma unroll
            for (int mt = 0; mt < 2; mt++) {
                int m1 = wm * 32 + mt * 16 + g;
                a[mt][0] = __float_as_uint(Ash[buf][k0    ][m1    ]);
                a[mt][1] = __float_as_uint(Ash[buf][k0    ][m1 + 8]);
                a[mt][2] = __float_as_uint(Ash[buf][k0 + 4][m1    ]);
                a[mt][3] = __float_as_uint(Ash[buf][k0 + 4][m1 + 8]);
            }
            uint32_t b[6][2];
#pragma unroll
            for (int nt = 0; nt < 6; nt++) {
                int n = wn * 48 + nt * 8 + g;
                b[nt][0] = __float_as_uint(Bsh[buf][k0    ][n]);
                b[nt][1] = __float_as_uint(Bsh[buf][k0 + 4][n]);
            }
#pragma unroll
            for (int mt = 0; mt < 2; mt++)
#pragma unroll
                for (int nt = 0; nt < 6; nt++)
                    mma_tf32(acc[mt][nt], a[mt], b[nt]);
        }

        if (s + 1 < NSTG) { ssts(buf ^ 1); __syncthreads(); }
    }

    // ---- epilogue: scatter with ALPHA ----
#pragma unroll
    for (int mt = 0; mt < 2; mt++) {
        const int Cr = c0 + wm * 32 + mt * 16 + g;
#pragma unroll
        for (int nt = 0; nt < 6; nt++) {
            const int jb = wn * 48 + nt * 8 + 2 * tg;
#pragma unroll
            for (int e = 0; e < 4; e++) {
                const int j = jb + (e & 1);
                const int C = Cr + (e >> 1) * 8;
                const int nl = j / 3, d = j % 3;
                int node = nodes[nl];
                if (node >= 0)
                    out[(size_t)node * (OUTC * MD) + C * MD + d] = acc[mt][nt][e] * ALPHA;
            }
        }
    }
}

// --------- entry point ----------
extern "C" void kernel_launch(void* const* d_in, const int* in_sizes, int n_in,
                              void* d_out, int out_size)
{
    const float* t     = (const float*)d_in[0];   // [B, IN, M]
    const float* attrs = (const float*)d_in[1];   // [B, Z]
    const float* W     = (const float*)d_in[2];   // [Z, OUT, IN]
    float* out = (float*)d_out;                   // [B, OUT, M]

    k_zero<<<1, 32>>>();
    k_classify<<<B_NODES / 256, 256>>>(attrs);
    k_scan<<<1, 1>>>();
    k_scatter<<<B_NODES / 256, 256>>>();

    dim3 grid(B_NODES / NT,   // 128 node tiles (over-launched; early exit)
              OUTC / CT,      // 4
              ZS);            // 10
    k_gemm<<<grid, NTHREADS>>>(t, W, out);
}

// round 5
// speedup vs baseline: 3.6316x; 1.2532x over previous
#include <cuda_runtime.h>
#include <cstdint>

#define B_NODES 8192
#define ZS      10
#define INC     512
#define OUTC    512
#define MD      3
#define ALPHA   0.04419417382415922f   // 1/sqrt(512)

#define NT      64                     // nodes per tile
#define NCOLS   (NT*MD)                // 192
#define CT      128                    // C tile
#define KT      32                     // k per stage
#define KSTAGES (INC/KT)               // 16
#define NTHREADS 512
#define TILES   138                    // max padded tiles: <=(8192+10*63)/64

#define ASTR 136                       // smem A row stride (==8 mod 32)
#define BSTR 200                       // smem B row stride (==8 mod 32)
#define A_F  (KT*ASTR)                 // 4352 floats
#define B_F  (KT*BSTR)                 // 6400 floats
#define STAGE_F (A_F+B_F)              // 10752 floats
#define GEMM_SMEM (4*STAGE_F*4)        // 172032 bytes
#define OSTR 388                       // epilogue smem row stride (97 float4)

// --------- scratch ----------
__device__ int g_counts[ZS];
__device__ int g_cursor[ZS];
__device__ int g_tilez[TILES];
__device__ int g_psorted[TILES * NT];
__device__ int g_species[B_NODES];
__device__ float Wt[(size_t)ZS * INC * OUTC];        // [z][k][c], tf32-rounded
__device__ float Bt[(size_t)TILES * INC * NCOLS];    // [tile][k][nl*3+d], tf32-rounded

// --------- helpers ----------
__device__ __forceinline__ uint32_t f2tf32(float f) {
    uint32_t r;
    asm("cvt.rna.tf32.f32 %0, %1;" : "=r"(r) : "f"(f));
    return r;
}
__device__ __forceinline__ float tf32v(float f) { return __uint_as_float(f2tf32(f)); }

__device__ __forceinline__ void cpa16(float* dst, const float* src) {
    uint32_t d = (uint32_t)__cvta_generic_to_shared(dst);
    asm volatile("cp.async.cg.shared.global [%0], [%1], 16;" :: "r"(d), "l"(src) : "memory");
}
__device__ __forceinline__ void mma_tf32(float* c, const uint32_t* a, const uint32_t* b) {
    asm volatile(
        "mma.sync.aligned.m16n8k8.row.col.f32.tf32.tf32.f32 "
        "{%0,%1,%2,%3}, {%4,%5,%6,%7}, {%8,%9}, {%0,%1,%2,%3};"
        : "+f"(c[0]), "+f"(c[1]), "+f"(c[2]), "+f"(c[3])
        : "r"(a[0]), "r"(a[1]), "r"(a[2]), "r"(a[3]), "r"(b[0]), "r"(b[1]));
}

// --------- prep ----------
__global__ void k_zero() {
    int i = threadIdx.x;
    if (i < ZS) { g_counts[i] = 0; g_cursor[i] = 0; }
}

__global__ void k_classify(const float* __restrict__ attrs) {
    __shared__ int h[ZS];
    int tid = threadIdx.x;
    if (tid < ZS) h[tid] = 0;
    __syncthreads();
    int b = blockIdx.x * blockDim.x + tid;
    int s = 0;
#pragma unroll
    for (int z = 0; z < ZS; z++)
        s = (attrs[b * ZS + z] > 0.5f) ? z : s;
    g_species[b] = s;
    atomicAdd(&h[s], 1);
    __syncthreads();
    if (tid < ZS) atomicAdd(&g_counts[tid], h[tid]);
}

__global__ void k_scan() {
    if (threadIdx.x == 0) {
        int acc = 0;
        for (int z = 0; z < ZS; z++) {
            g_cursor[z] = acc;                       // padded segment start
            int tiles = (g_counts[z] + NT - 1) / NT;
            for (int ti = 0; ti < tiles; ti++) g_tilez[acc / NT + ti] = z;
            acc += tiles * NT;
        }
        for (int ti = acc / NT; ti < TILES; ti++) g_tilez[ti] = -1;
    }
}

__global__ void k_fill() {
    int i = blockIdx.x * blockDim.x + threadIdx.x;
    if (i < TILES * NT) g_psorted[i] = -1;
}

__global__ void k_scatter() {
    __shared__ int h[ZS], base[ZS];
    int tid = threadIdx.x;
    if (tid < ZS) h[tid] = 0;
    __syncthreads();
    int b = blockIdx.x * blockDim.x + tid;
    int s = g_species[b];
    int lp = atomicAdd(&h[s], 1);
    __syncthreads();
    if (tid < ZS) base[tid] = atomicAdd(&g_cursor[tid], h[tid]);
    __syncthreads();
    g_psorted[base[s] + lp] = b;
}

// --------- W transpose + tf32 convert: Wt[z][k][c] ----------
__global__ void k_wt(const float* __restrict__ W) {
    __shared__ float tl[32][33];
    int z = blockIdx.z;
    const float* src = W + ((size_t)z * OUTC + blockIdx.y * 32) * INC + blockIdx.x * 32;
    int tx = threadIdx.x, ty = threadIdx.y;
#pragma unroll
    for (int j = 0; j < 4; j++)
        tl[ty + j * 8][tx] = tf32v(src[(ty + j * 8) * INC + tx]);   // tl[c][k]
    __syncthreads();
    float* dst = Wt + ((size_t)z * INC + blockIdx.x * 32) * OUTC + blockIdx.y * 32;
#pragma unroll
    for (int j = 0; j < 4; j++)
        dst[(ty + j * 8) * OUTC + tx] = tl[tx][ty + j * 8];         // Wt[k][c]
}

// --------- t gather + tf32 convert + transpose: Bt[tile][k][nl*3+d] ----------
#define SHB 196
__global__ void k_bt(const float* __restrict__ t) {
    int tile = blockIdx.x;
    if (g_tilez[tile] < 0) return;
    int kc = blockIdx.y;                     // 64-k chunk (8 per tile)
    extern __shared__ float sh[];            // [64 nodes][196]
    int tid = threadIdx.x;
#pragma unroll
    for (int i = 0; i < 12; i++) {
        int idx = i * 256 + tid;             // 3072 float4s
        int nl = idx / 48, f4 = idx % 48;
        int node = g_psorted[tile * NT + nl];
        float4 v = make_float4(0.f, 0.f, 0.f, 0.f);
        if (node >= 0)
            v = *(const float4*)(t + (size_t)node * (INC * MD) + kc * 192 + f4 * 4);
        int base = nl * SHB + f4 * 4;
        sh[base + 0] = tf32v(v.x); sh[base + 1] = tf32v(v.y);
        sh[base + 2] = tf32v(v.z); sh[base + 3] = tf32v(v.w);
    }
    __syncthreads();
    float* dst = Bt + ((size_t)tile * INC + kc * 64) * NCOLS;
#pragma unroll
    for (int i = 0; i < 12; i++) {
        int idx = i * 256 + tid;
        int k = idx / 48, f4 = idx % 48;
        float4 v;
        int c0 = f4 * 4;
        v.x = sh[((c0 + 0) / 3) * SHB + k * 3 + (c0 + 0) % 3];
        v.y = sh[((c0 + 1) / 3) * SHB + k * 3 + (c0 + 1) % 3];
        v.z = sh[((c0 + 2) / 3) * SHB + k * 3 + (c0 + 2) % 3];
        v.w = sh[((c0 + 3) / 3) * SHB + k * 3 + (c0 + 3) % 3];
        *(float4*)(dst + k * NCOLS + f4 * 4) = v;
    }
}

// --------- GEMM: cp.async pipeline + mma.sync tf32 ----------
__global__ __launch_bounds__(NTHREADS, 1)
void k_gemm(float* __restrict__ out)
{
    const int tile = blockIdx.x;
    const int z = g_tilez[tile];
    if (z < 0) return;
    const int c0 = blockIdx.y * CT;

    extern __shared__ float sm[];
    __shared__ int nodes_s[NT];

    const int tid = threadIdx.x;
    if (tid < NT) nodes_s[tid] = g_psorted[tile * NT + tid];

    const int lane = tid & 31;
    const int wid  = tid >> 5;
    const int wm   = wid & 3;
    const int wn   = wid >> 2;
    const int g    = lane >> 2;
    const int tg   = lane & 3;

    const float* abase = Wt + (size_t)z * INC * OUTC + c0;
    const float* bbase = Bt + (size_t)tile * INC * NCOLS;

    auto issue = [&](int s) {
        float* abuf = sm + (s & 3) * STAGE_F;
        const float* asrc = abase + (size_t)(s * KT) * OUTC;
#pragma unroll
        for (int i = 0; i < 2; i++) {
            int idx = i * NTHREADS + tid;          // 1024 chunks
            int row = idx >> 5, ch = idx & 31;
            cpa16(abuf + row * ASTR + ch * 4, asrc + row * OUTC + ch * 4);
        }
        float* bbuf = abuf + A_F;
        const float* bsrc = bbase + (size_t)(s * KT) * NCOLS;
#pragma unroll
        for (int i = 0; i < 3; i++) {
            int idx = i * NTHREADS + tid;          // 1536 chunks
            int row = idx / 48, ch = idx % 48;
            cpa16(bbuf + row * BSTR + ch * 4, bsrc + row * NCOLS + ch * 4);
        }
    };

    issue(0); asm volatile("cp.async.commit_group;" ::: "memory");
    issue(1); asm volatile("cp.async.commit_group;" ::: "memory");
    issue(2); asm volatile("cp.async.commit_group;" ::: "memory");

    float acc[2][6][4];
#pragma unroll
    for (int i = 0; i < 2; i++)
#pragma unroll
        for (int j = 0; j < 6; j++)
#pragma unroll
            for (int e = 0; e < 4; e++) acc[i][j][e] = 0.f;

    for (int s = 0; s < KSTAGES; s++) {
        asm volatile("cp.async.wait_group 2;" ::: "memory");
        __syncthreads();
        if (s + 3 < KSTAGES) issue(s + 3);
        asm volatile("cp.async.commit_group;" ::: "memory");

        const float* ab = sm + (s & 3) * STAGE_F;
        const float* bb = ab + A_F;
#pragma unroll
        for (int kc = 0; kc < 4; kc++) {
            const int k0 = kc * 8 + tg;
            uint32_t a[2][4];
#pragma unroll
            for (int mt = 0; mt < 2; mt++) {
                int m1 = wm * 32 + mt * 16 + g;
                a[mt][0] = __float_as_uint(ab[k0 * ASTR + m1]);
                a[mt][1] = __float_as_uint(ab[k0 * ASTR + m1 + 8]);
                a[mt][2] = __float_as_uint(ab[(k0 + 4) * ASTR + m1]);
                a[mt][3] = __float_as_uint(ab[(k0 + 4) * ASTR + m1 + 8]);
            }
            uint32_t b[6][2];
#pragma unroll
            for (int nt = 0; nt < 6; nt++) {
                int n = wn * 48 + nt * 8 + g;
                b[nt][0] = __float_as_uint(bb[k0 * BSTR + n]);
                b[nt][1] = __float_as_uint(bb[(k0 + 4) * BSTR + n]);
            }
#pragma unroll
            for (int mt = 0; mt < 2; mt++)
#pragma unroll
                for (int nt = 0; nt < 6; nt++)
                    mma_tf32(acc[mt][nt], a[mt], b[nt]);
        }
    }

    // ---- epilogue: acc -> smem [node][C*3+d] -> coalesced out ----
    __syncthreads();
#pragma unroll
    for (int mt = 0; mt < 2; mt++) {
#pragma unroll
        for (int nt = 0; nt < 6; nt++) {
#pragma unroll
            for (int e = 0; e < 4; e++) {
                int Cl = wm * 32 + mt * 16 + g + (e >> 1) * 8;
                int j  = wn * 48 + nt * 8 + 2 * tg + (e & 1);
                int nl = j / 3, d = j - nl * 3;
                sm[nl * OSTR + Cl * 3 + d] = acc[mt][nt][e] * ALPHA;
            }
        }
    }
    __syncthreads();
#pragma unroll
    for (int i = 0; i < 12; i++) {
        int idx = i * NTHREADS + tid;              // 6144 float4s
        int nl = idx / 96, f4 = idx % 96;
        int node = nodes_s[nl];
        if (node >= 0) {
            float4 v = *(const float4*)(sm + nl * OSTR + f4 * 4);
            *(float4*)(out + (size_t)node * (OUTC * MD) + c0 * 3 + f4 * 4) = v;
        }
    }
}

// --------- entry point ----------
extern "C" void kernel_launch(void* const* d_in, const int* in_sizes, int n_in,
                              void* d_out, int out_size)
{
    const float* t     = (const float*)d_in[0];   // [B, IN, M]
    const float* attrs = (const float*)d_in[1];   // [B, Z]
    const float* W     = (const float*)d_in[2];   // [Z, OUT, IN]
    float* out = (float*)d_out;                   // [B, OUT, M]

    k_zero<<<1, 32>>>();
    k_classify<<<B_NODES / 256, 256>>>(attrs);
    k_scan<<<1, 1>>>();
    k_fill<<<(TILES * NT + 255) / 256, 256>>>();
    k_scatter<<<B_NODES / 256, 256>>>();

    k_wt<<<dim3(INC / 32, OUTC / 32, ZS), dim3(32, 8)>>>(W);

    cudaFuncSetAttribute(k_bt, cudaFuncAttributeMaxDynamicSharedMemorySize, NT * SHB * 4);
    k_bt<<<dim3(TILES, 8), 256, NT * SHB * 4>>>(t);

    cudaFuncSetAttribute(k_gemm, cudaFuncAttributeMaxDynamicSharedMemorySize, GEMM_SMEM);
    k_gemm<<<dim3(TILES, OUTC / CT), NTHREADS, GEMM_SMEM>>>(out);
}

// round 6
// speedup vs baseline: 3.9695x; 1.0930x over previous
#include <cuda_runtime.h>
#include <cstdint>

#define B_NODES 8192
#define ZS      10
#define INC     512
#define OUTC    512
#define MD      3
#define ALPHA   0.04419417382415922f   // 1/sqrt(512)

#define NT      64                     // nodes per tile
#define NCOLS   (NT*MD)                // 192
#define CT      128                    // C tile
#define KT      32                     // k per stage
#define KSTAGES (INC/KT)               // 16
#define NTHREADS 512
#define TILES   138

#define A_F       (CT*KT)              // 4096 floats (128 rows x 128B)
#define B_F       (NCOLS*KT)           // 6144 floats
#define STAGE_F   (A_F+B_F)            // 10240 floats
#define A_BYTES   (A_F*4)              // 16384
#define STAGE_BYTES (STAGE_F*4)        // 40960
#define GEMM_SMEM (4*STAGE_BYTES)      // 163840
#define OSTR 388                       // epilogue smem row stride (floats)

// --------- scratch ----------
__device__ int g_counts[ZS];
__device__ int g_cursor[ZS];
__device__ int g_tilez[TILES];
__device__ int g_psorted[TILES * NT];
__device__ int g_species[B_NODES];
__device__ float Wc[(size_t)ZS * OUTC * INC];        // [z][c][k], tf32-rounded
__device__ float Bt[(size_t)TILES * NCOLS * INC];    // [tile][n][k], tf32-rounded

// --------- helpers ----------
__device__ __forceinline__ uint32_t f2tf32(float f) {
    uint32_t r;
    asm("cvt.rna.tf32.f32 %0, %1;" : "=r"(r) : "f"(f));
    return r;
}
__device__ __forceinline__ float tf32v(float f) { return __uint_as_float(f2tf32(f)); }

__device__ __forceinline__ void cpa16(float* dst, const float* src) {
    uint32_t d = (uint32_t)__cvta_generic_to_shared(dst);
    asm volatile("cp.async.cg.shared.global [%0], [%1], 16;" :: "r"(d), "l"(src) : "memory");
}
#define LDSM_X4(r, a) \
    asm volatile("ldmatrix.sync.aligned.m8n8.x4.shared.b16 {%0,%1,%2,%3}, [%4];" \
        : "=r"((r)[0]), "=r"((r)[1]), "=r"((r)[2]), "=r"((r)[3]) : "r"(a))

__device__ __forceinline__ void mma_tf32(float* c, const uint32_t* a, const uint32_t* b) {
    asm volatile(
        "mma.sync.aligned.m16n8k8.row.col.f32.tf32.tf32.f32 "
        "{%0,%1,%2,%3}, {%4,%5,%6,%7}, {%8,%9}, {%0,%1,%2,%3};"
        : "+f"(c[0]), "+f"(c[1]), "+f"(c[2]), "+f"(c[3])
        : "r"(a[0]), "r"(a[1]), "r"(a[2]), "r"(a[3]), "r"(b[0]), "r"(b[1]));
}

// --------- prep ----------
__global__ void k_zero() {
    int i = threadIdx.x;
    if (i < ZS) { g_counts[i] = 0; g_cursor[i] = 0; }
}

__global__ void k_classify(const float* __restrict__ attrs) {
    __shared__ int h[ZS];
    int tid = threadIdx.x;
    if (tid < ZS) h[tid] = 0;
    __syncthreads();
    int b = blockIdx.x * blockDim.x + tid;
    int s = 0;
#pragma unroll
    for (int z = 0; z < ZS; z++)
        s = (attrs[b * ZS + z] > 0.5f) ? z : s;
    g_species[b] = s;
    atomicAdd(&h[s], 1);
    __syncthreads();
    if (tid < ZS) atomicAdd(&g_counts[tid], h[tid]);
}

__global__ void k_scanfill() {
    int tid = threadIdx.x;
    if (tid == 0) {
        int acc = 0;
        for (int z = 0; z < ZS; z++) {
            g_cursor[z] = acc;
            int tiles = (g_counts[z] + NT - 1) / NT;
            for (int ti = 0; ti < tiles; ti++) g_tilez[acc / NT + ti] = z;
            acc += tiles * NT;
        }
        for (int ti = acc / NT; ti < TILES; ti++) g_tilez[ti] = -1;
    }
    for (int i = tid; i < TILES * NT; i += blockDim.x) g_psorted[i] = -1;
}

__global__ void k_scatter() {
    __shared__ int h[ZS], base[ZS];
    int tid = threadIdx.x;
    if (tid < ZS) h[tid] = 0;
    __syncthreads();
    int b = blockIdx.x * blockDim.x + tid;
    int s = g_species[b];
    int lp = atomicAdd(&h[s], 1);
    __syncthreads();
    if (tid < ZS) base[tid] = atomicAdd(&g_cursor[tid], h[tid]);
    __syncthreads();
    g_psorted[base[s] + lp] = b;
}

// --------- W tf32-round (no transpose): Wc[z][c][k] ----------
__global__ void k_wc(const float* __restrict__ W) {
    size_t i = ((size_t)blockIdx.x * blockDim.x + threadIdx.x) * 4;
    float4 v = *(const float4*)(W + i);
    v.x = tf32v(v.x); v.y = tf32v(v.y); v.z = tf32v(v.z); v.w = tf32v(v.w);
    *(float4*)(Wc + i) = v;
}

// --------- t gather + round + transpose: Bt[tile][nl*3+d][k] ----------
#define SHB 196
__global__ void k_bt(const float* __restrict__ t) {
    int tile = blockIdx.x;
    if (g_tilez[tile] < 0) return;
    int kc = blockIdx.y;                     // 64-k chunk (8 per tile)
    extern __shared__ float sh[];            // [64 nodes][196]
    int tid = threadIdx.x;
#pragma unroll
    for (int i = 0; i < 12; i++) {
        int idx = i * 256 + tid;             // 3072 float4s
        int nl = idx / 48, f4 = idx % 48;
        int node = g_psorted[tile * NT + nl];
        float4 v = make_float4(0.f, 0.f, 0.f, 0.f);
        if (node >= 0)
            v = *(const float4*)(t + (size_t)node * (INC * MD) + kc * 192 + f4 * 4);
        int base = nl * SHB + f4 * 4;
        sh[base + 0] = tf32v(v.x); sh[base + 1] = tf32v(v.y);
        sh[base + 2] = tf32v(v.z); sh[base + 3] = tf32v(v.w);
    }
    __syncthreads();
    float* dst = Bt + (size_t)tile * NCOLS * INC + kc * 64;
#pragma unroll
    for (int i = 0; i < 12; i++) {
        int idx = i * 256 + tid;             // 192 n-rows x 16 float4
        int n = idx / 16, kq = idx % 16;
        int nl = n / 3, d = n % 3;
        float4 v;
        v.x = sh[nl * SHB + (kq * 4 + 0) * 3 + d];
        v.y = sh[nl * SHB + (kq * 4 + 1) * 3 + d];
        v.z = sh[nl * SHB + (kq * 4 + 2) * 3 + d];
        v.w = sh[nl * SHB + (kq * 4 + 3) * 3 + d];
        *(float4*)(dst + (size_t)n * INC + kq * 4) = v;
    }
}

// --------- GEMM: cp.async pipeline + ldmatrix + mma.sync tf32 ----------
__global__ __launch_bounds__(NTHREADS, 1)
void k_gemm(float* __restrict__ out)
{
    const int tile = blockIdx.x;
    const int z = g_tilez[tile];
    if (z < 0) return;
    const int c0 = blockIdx.y * CT;

    extern __shared__ float sm[];
    __shared__ int nodes_s[NT];

    const int tid = threadIdx.x;
    if (tid < NT) nodes_s[tid] = g_psorted[tile * NT + tid];

    const int lane = tid & 31;
    const int wid  = tid >> 5;
    const int wm   = wid & 3;
    const int wn   = wid >> 2;
    const int g    = lane >> 2;
    const int tg   = lane & 3;

    const float* abase = Wc + ((size_t)z * OUTC + c0) * INC;
    const float* bbase = Bt + (size_t)tile * NCOLS * INC;

    auto issue = [&](int s) {
        float* ab = sm + (s & 3) * STAGE_F;
        const float* asrc = abase + s * KT;
#pragma unroll
        for (int i = 0; i < 2; i++) {
            int idx = i * NTHREADS + tid;          // 1024 chunks
            int m = idx >> 3, c16 = idx & 7;
            cpa16(ab + m * 32 + ((c16 ^ (m & 7)) << 2), asrc + (size_t)m * INC + c16 * 4);
        }
        float* bb = ab + A_F;
        const float* bsrc = bbase + s * KT;
#pragma unroll
        for (int i = 0; i < 3; i++) {
            int idx = i * NTHREADS + tid;          // 1536 chunks
            int n = idx >> 3, c16 = idx & 7;
            cpa16(bb + n * 32 + ((c16 ^ (n & 7)) << 2), bsrc + (size_t)n * INC + c16 * 4);
        }
    };

    issue(0); asm volatile("cp.async.commit_group;" ::: "memory");
    issue(1); asm volatile("cp.async.commit_group;" ::: "memory");
    issue(2); asm volatile("cp.async.commit_group;" ::: "memory");

    // ---- per-lane ldmatrix row addressing (byte offsets, swizzled per kc) ----
    const int mi = lane >> 3;                      // matrix index 0..3
    const int mr = lane & 7;                       // row within matrix
    uint32_t aoff[2], a7[2];
#pragma unroll
    for (int mt = 0; mt < 2; mt++) {
        int m = wm * 32 + mt * 16 + (mi & 1) * 8 + mr;
        aoff[mt] = (uint32_t)m * 128;
        a7[mt] = (uint32_t)(m & 7);
    }
    const uint32_t akhi = (uint32_t)(mi >> 1);
    uint32_t boff[3], b7[3];
#pragma unroll
    for (int p = 0; p < 3; p++) {
        int n = wn * 48 + p * 16 + (mi >> 1) * 8 + mr;
        boff[p] = (uint32_t)n * 128;
        b7[p] = (uint32_t)(n & 7);
    }
    const uint32_t bkhi = (uint32_t)(mi & 1);
    const uint32_t smbase = (uint32_t)__cvta_generic_to_shared(sm);

    float acc[2][6][4];
#pragma unroll
    for (int i = 0; i < 2; i++)
#pragma unroll
        for (int j = 0; j < 6; j++)
#pragma unroll
            for (int e = 0; e < 4; e++) acc[i][j][e] = 0.f;

    for (int s = 0; s < KSTAGES; s++) {
        asm volatile("cp.async.wait_group 2;" ::: "memory");
        __syncthreads();
        if (s + 3 < KSTAGES) issue(s + 3);
        asm volatile("cp.async.commit_group;" ::: "memory");

        const uint32_t sA = smbase + (s & 3) * STAGE_BYTES;
        const uint32_t sB = sA + A_BYTES;
#pragma unroll
        for (int kc = 0; kc < 4; kc++) {
            uint32_t a[2][4];
#pragma unroll
            for (int mt = 0; mt < 2; mt++)
                LDSM_X4(a[mt], sA + aoff[mt] + ((((uint32_t)kc * 2 + akhi) ^ a7[mt]) << 4));
            uint32_t b[3][4];
#pragma unroll
            for (int p = 0; p < 3; p++)
                LDSM_X4(b[p], sB + boff[p] + ((((uint32_t)kc * 2 + bkhi) ^ b7[p]) << 4));
#pragma unroll
            for (int mt = 0; mt < 2; mt++)
#pragma unroll
                for (int nt = 0; nt < 6; nt++)
                    mma_tf32(acc[mt][nt], a[mt], b[nt >> 1] + (nt & 1) * 2);
        }
    }

    // ---- epilogue: acc -> smem [node][C*3+d] -> coalesced out ----
    __syncthreads();
#pragma unroll
    for (int mt = 0; mt < 2; mt++) {
#pragma unroll
        for (int nt = 0; nt < 6; nt++) {
#pragma unroll
            for (int e = 0; e < 4; e++) {
                int Cl = wm * 32 + mt * 16 + g + (e >> 1) * 8;
                int j  = wn * 48 + nt * 8 + 2 * tg + (e & 1);
                int nl = j / 3, d = j - nl * 3;
                sm[nl * OSTR + Cl * 3 + d] = acc[mt][nt][e] * ALPHA;
            }
        }
    }
    __syncthreads();
#pragma unroll
    for (int i = 0; i < 12; i++) {
        int idx = i * NTHREADS + tid;              // 6144 float4s
        int nl = idx / 96, f4 = idx % 96;
        int node = nodes_s[nl];
        if (node >= 0) {
            float4 v = *(const float4*)(sm + nl * OSTR + f4 * 4);
            *(float4*)(out + (size_t)node * (OUTC * MD) + c0 * 3 + f4 * 4) = v;
        }
    }
}

// --------- entry point ----------
extern "C" void kernel_launch(void* const* d_in, const int* in_sizes, int n_in,
                              void* d_out, int out_size)
{
    const float* t     = (const float*)d_in[0];   // [B, IN, M]
    const float* attrs = (const float*)d_in[1];   // [B, Z]
    const float* W     = (const float*)d_in[2];   // [Z, OUT, IN]
    float* out = (float*)d_out;                   // [B, OUT, M]

    k_zero<<<1, 32>>>();
    k_classify<<<B_NODES / 256, 256>>>(attrs);
    k_scanfill<<<1, 256>>>();
    k_scatter<<<B_NODES / 256, 256>>>();

    k_wc<<<(ZS * OUTC * INC) / (256 * 4), 256>>>(W);

    cudaFuncSetAttribute(k_bt, cudaFuncAttributeMaxDynamicSharedMemorySize, NT * SHB * 4);
    k_bt<<<dim3(TILES, 8), 256, NT * SHB * 4>>>(t);

    cudaFuncSetAttribute(k_gemm, cudaFuncAttributeMaxDynamicSharedMemorySize, GEMM_SMEM);
    k_gemm<<<dim3(TILES, OUTC / CT), NTHREADS, GEMM_SMEM>>>(out);
}

// round 7
// speedup vs baseline: 6.0117x; 1.5145x over previous
#include <cuda_runtime.h>
#include <cuda_fp16.h>
#include <cstdint>

#define B_NODES 8192
#define ZS      10
#define INC     512
#define OUTC    512
#define MD      3
#define ALPHA   0.04419417382415922f   // 1/sqrt(512)

#define NT      64                     // nodes per tile
#define NCOLS   (NT*MD)                // 192
#define CT      128                    // C tile
#define KT      32                     // k (halves) per stage
#define KSTAGES (INC/KT)               // 16
#define NSTAGES 6                      // smem ring depth
#define NTHREADS 512
#define TILES   138

#define A_BYTES    (CT*KT*2)           // 8192
#define B_BYTES    (NCOLS*KT*2)        // 12288
#define STAGE_BYTES (A_BYTES+B_BYTES)  // 20480
#define GEMM_SMEM  (NSTAGES*STAGE_BYTES) // 122880
#define OSTR 388                       // epilogue smem row stride (floats)

// --------- scratch ----------
__device__ int g_counts[ZS];
__device__ int g_cursor[ZS];
__device__ int g_tilez[TILES];
__device__ int g_psorted[TILES * NT];
__device__ int g_species[B_NODES];
__device__ __half Wh[(size_t)ZS * OUTC * INC];       // [z][c][k] fp16
__device__ __half Bh[(size_t)TILES * NCOLS * INC];   // [tile][n][k] fp16

// --------- helpers ----------
__device__ __forceinline__ void cpa16(void* dst, const void* src) {
    uint32_t d = (uint32_t)__cvta_generic_to_shared(dst);
    asm volatile("cp.async.cg.shared.global [%0], [%1], 16;" :: "r"(d), "l"(src) : "memory");
}
#define LDSM_X4(r, a) \
    asm volatile("ldmatrix.sync.aligned.m8n8.x4.shared.b16 {%0,%1,%2,%3}, [%4];" \
        : "=r"((r)[0]), "=r"((r)[1]), "=r"((r)[2]), "=r"((r)[3]) : "r"(a))

__device__ __forceinline__ void mma_f16(float* c, const uint32_t* a, const uint32_t* b) {
    asm volatile(
        "mma.sync.aligned.m16n8k16.row.col.f32.f16.f16.f32 "
        "{%0,%1,%2,%3}, {%4,%5,%6,%7}, {%8,%9}, {%0,%1,%2,%3};"
        : "+f"(c[0]), "+f"(c[1]), "+f"(c[2]), "+f"(c[3])
        : "r"(a[0]), "r"(a[1]), "r"(a[2]), "r"(a[3]), "r"(b[0]), "r"(b[1]));
}

// --------- prep ----------
__global__ void k_zero() {
    int i = threadIdx.x;
    if (i < ZS) { g_counts[i] = 0; g_cursor[i] = 0; }
}

__global__ void k_classify(const float* __restrict__ attrs) {
    __shared__ int h[ZS];
    int tid = threadIdx.x;
    if (tid < ZS) h[tid] = 0;
    __syncthreads();
    int b = blockIdx.x * blockDim.x + tid;
    int s = 0;
#pragma unroll
    for (int z = 0; z < ZS; z++)
        s = (attrs[b * ZS + z] > 0.5f) ? z : s;
    g_species[b] = s;
    atomicAdd(&h[s], 1);
    __syncthreads();
    if (tid < ZS) atomicAdd(&g_counts[tid], h[tid]);
}

__global__ void k_scanfill() {
    int tid = threadIdx.x;
    if (tid == 0) {
        int acc = 0;
        for (int z = 0; z < ZS; z++) {
            g_cursor[z] = acc;
            int tiles = (g_counts[z] + NT - 1) / NT;
            for (int ti = 0; ti < tiles; ti++) g_tilez[acc / NT + ti] = z;
            acc += tiles * NT;
        }
        for (int ti = acc / NT; ti < TILES; ti++) g_tilez[ti] = -1;
    }
    for (int i = tid; i < TILES * NT; i += blockDim.x) g_psorted[i] = -1;
}

__global__ void k_scatter() {
    __shared__ int h[ZS], base[ZS];
    int tid = threadIdx.x;
    if (tid < ZS) h[tid] = 0;
    __syncthreads();
    int b = blockIdx.x * blockDim.x + tid;
    int s = g_species[b];
    int lp = atomicAdd(&h[s], 1);
    __syncthreads();
    if (tid < ZS) base[tid] = atomicAdd(&g_cursor[tid], h[tid]);
    __syncthreads();
    g_sorted_dummy:
    g_psorted[base[s] + lp] = b;
}

// --------- W -> fp16: Wh[z][c][k] ----------
__global__ void k_wh(const float* __restrict__ W) {
    size_t i = ((size_t)blockIdx.x * blockDim.x + threadIdx.x) * 8;
    float4 v0 = *(const float4*)(W + i);
    float4 v1 = *(const float4*)(W + i + 4);
    __half2 h[4];
    h[0] = __floats2half2_rn(v0.x, v0.y);
    h[1] = __floats2half2_rn(v0.z, v0.w);
    h[2] = __floats2half2_rn(v1.x, v1.y);
    h[3] = __floats2half2_rn(v1.z, v1.w);
    *(uint4*)(Wh + i) = *(uint4*)h;
}

// --------- t gather + fp16 + transpose: Bh[tile][nl*3+d][k] ----------
#define SHB 196
__global__ void k_bh(const float* __restrict__ t) {
    int tile = blockIdx.x;
    if (g_tilez[tile] < 0) return;
    int kc = blockIdx.y;                     // 64-k chunk (8 per tile)
    extern __shared__ float sh[];            // [64 nodes][196]
    int tid = threadIdx.x;
#pragma unroll
    for (int i = 0; i < 12; i++) {
        int idx = i * 256 + tid;             // 3072 float4s
        int nl = idx / 48, f4 = idx % 48;
        int node = g_psorted[tile * NT + nl];
        float4 v = make_float4(0.f, 0.f, 0.f, 0.f);
        if (node >= 0)
            v = *(const float4*)(t + (size_t)node * (INC * MD) + kc * 192 + f4 * 4);
        int base = nl * SHB + f4 * 4;
        sh[base + 0] = v.x; sh[base + 1] = v.y;
        sh[base + 2] = v.z; sh[base + 3] = v.w;
    }
    __syncthreads();
    __half* dst = Bh + (size_t)tile * NCOLS * INC + kc * 64;
#pragma unroll
    for (int i = 0; i < 12; i++) {
        int idx = i * 256 + tid;             // 192 n-rows x 16 quad-groups
        int n = idx / 16, kq = idx % 16;
        int nl = n / 3, d = n % 3;
        float x = sh[nl * SHB + (kq * 4 + 0) * 3 + d];
        float y = sh[nl * SHB + (kq * 4 + 1) * 3 + d];
        float zv = sh[nl * SHB + (kq * 4 + 2) * 3 + d];
        float w = sh[nl * SHB + (kq * 4 + 3) * 3 + d];
        __half2 p[2];
        p[0] = __floats2half2_rn(x, y);
        p[1] = __floats2half2_rn(zv, w);
        *(uint2*)(dst + (size_t)n * INC + kq * 4) = *(uint2*)p;
    }
}

// --------- GEMM: cp.async 6-stage ring + ldmatrix + fp16 mma ----------
__global__ __launch_bounds__(NTHREADS, 1)
void k_gemm(float* __restrict__ out)
{
    const int tile = blockIdx.x;
    const int z = g_tilez[tile];
    if (z < 0) return;
    const int c0 = blockIdx.y * CT;

    extern __shared__ float sm[];
    char* smc = (char*)sm;
    __shared__ int nodes_s[NT];

    const int tid = threadIdx.x;
    if (tid < NT) nodes_s[tid] = g_psorted[tile * NT + tid];

    const int lane = tid & 31;
    const int wid  = tid >> 5;
    const int wm   = wid & 3;
    const int wn   = wid >> 2;
    const int g    = lane >> 2;
    const int tg   = lane & 3;

    const __half* abase = Wh + ((size_t)z * OUTC + c0) * INC;
    const __half* bbase = Bh + (size_t)tile * NCOLS * INC;

    // A: 512 16B-chunks/stage (128 rows x 4), B: 768 (192 rows x 4)
    auto issue = [&](int s) {
        char* ab = smc + (s % NSTAGES) * STAGE_BYTES;
        const __half* asrc = abase + s * KT;
        {
            int m = tid >> 2, c = tid & 3;
            cpa16(ab + m * 64 + ((c ^ ((m >> 1) & 3)) << 4),
                  asrc + (size_t)m * INC + c * 8);
        }
        char* bb = ab + A_BYTES;
        const __half* bsrc = bbase + s * KT;
#pragma unroll
        for (int i = 0; i < 2; i++) {
            int idx = i * NTHREADS + tid;
            if (idx < 768) {
                int n = idx >> 2, c = idx & 3;
                cpa16(bb + n * 64 + ((c ^ ((n >> 1) & 3)) << 4),
                      bsrc + (size_t)n * INC + c * 8);
            }
        }
    };

#pragma unroll
    for (int p = 0; p < NSTAGES - 1; p++) {
        issue(p);
        asm volatile("cp.async.commit_group;" ::: "memory");
    }

    // ---- per-lane ldmatrix addressing ----
    const int mi = lane >> 3;              // matrix index 0..3 within x4
    const int mr = lane & 7;
    uint32_t aoff[2], a3[2];
#pragma unroll
    for (int mt = 0; mt < 2; mt++) {
        int m = wm * 32 + mt * 16 + (mi & 1) * 8 + mr;
        aoff[mt] = (uint32_t)m * 64;
        a3[mt] = (uint32_t)((m >> 1) & 3);
    }
    const uint32_t akc = (uint32_t)(mi >> 1);   // A chunk low bit from matrix idx
    uint32_t boff[3], b3[3];
#pragma unroll
    for (int p = 0; p < 3; p++) {
        int n = wn * 48 + p * 16 + (mi >> 1) * 8 + mr;
        boff[p] = (uint32_t)n * 64;
        b3[p] = (uint32_t)((n >> 1) & 3);
    }
    const uint32_t bkc = (uint32_t)(mi & 1);
    const uint32_t smbase = (uint32_t)__cvta_generic_to_shared(sm);

    float acc[2][6][4];
#pragma unroll
    for (int i = 0; i < 2; i++)
#pragma unroll
        for (int j = 0; j < 6; j++)
#pragma unroll
            for (int e = 0; e < 4; e++) acc[i][j][e] = 0.f;

    for (int s = 0; s < KSTAGES; s++) {
        asm volatile("cp.async.wait_group %0;" :: "n"(NSTAGES - 2) : "memory");
        __syncthreads();
        if (s + NSTAGES - 1 < KSTAGES) issue(s + NSTAGES - 1);
        asm volatile("cp.async.commit_group;" ::: "memory");

        const uint32_t sA = smbase + (s % NSTAGES) * STAGE_BYTES;
        const uint32_t sB = sA + A_BYTES;
#pragma unroll
        for (int kc = 0; kc < 2; kc++) {
            uint32_t a[2][4];
#pragma unroll
            for (int mt = 0; mt < 2; mt++)
                LDSM_X4(a[mt], sA + aoff[mt] + (((((uint32_t)kc << 1) + akc) ^ a3[mt]) << 4));
            uint32_t b[3][4];
#pragma unroll
            for (int p = 0; p < 3; p++)
                LDSM_X4(b[p], sB + boff[p] + (((((uint32_t)kc << 1) + bkc) ^ b3[p]) << 4));
#pragma unroll
            for (int mt = 0; mt < 2; mt++)
#pragma unroll
                for (int nt = 0; nt < 6; nt++)
                    mma_f16(acc[mt][nt], a[mt], b[nt >> 1] + (nt & 1) * 2);
        }
    }

    // ---- epilogue: acc -> smem [node][C*3+d] -> coalesced out ----
    __syncthreads();
#pragma unroll
    for (int mt = 0; mt < 2; mt++) {
#pragma unroll
        for (int nt = 0; nt < 6; nt++) {
#pragma unroll
            for (int e = 0; e < 4; e++) {
                int Cl = wm * 32 + mt * 16 + g + (e >> 1) * 8;
                int j  = wn * 48 + nt * 8 + 2 * tg + (e & 1);
                int nl = j / 3, d = j - nl * 3;
                sm[nl * OSTR + Cl * 3 + d] = acc[mt][nt][e] * ALPHA;
            }
        }
    }
    __syncthreads();
#pragma unroll
    for (int i = 0; i < 12; i++) {
        int idx = i * NTHREADS + tid;              // 6144 float4s
        int nl = idx / 96, f4 = idx % 96;
        int node = nodes_s[nl];
        if (node >= 0) {
            float4 v = *(const float4*)(sm + nl * OSTR + f4 * 4);
            *(float4*)(out + (size_t)node * (OUTC * MD) + c0 * 3 + f4 * 4) = v;
        }
    }
}

// --------- entry point ----------
extern "C" void kernel_launch(void* const* d_in, const int* in_sizes, int n_in,
                              void* d_out, int out_size)
{
    const float* t     = (const float*)d_in[0];   // [B, IN, M]
    const float* attrs = (const float*)d_in[1];   // [B, Z]
    const float* W     = (const float*)d_in[2];   // [Z, OUT, IN]
    float* out = (float*)d_out;                   // [B, OUT, M]

    k_zero<<<1, 32>>>();
    k_classify<<<B_NODES / 256, 256>>>(attrs);
    k_scanfill<<<1, 256>>>();
    k_scatter<<<B_NODES / 256, 256>>>();

    k_wh<<<(ZS * OUTC * INC) / (256 * 8), 256>>>(W);

    cudaFuncSetAttribute(k_bh, cudaFuncAttributeMaxDynamicSharedMemorySize, NT * SHB * 4);
    k_bh<<<dim3(TILES, 8), 256, NT * SHB * 4>>>(t);

    cudaFuncSetAttribute(k_gemm, cudaFuncAttributeMaxDynamicSharedMemorySize, GEMM_SMEM);
    k_gemm<<<dim3(TILES, OUTC / CT), NTHREADS, GEMM_SMEM>>>(out);
}